// round 14
// baseline (speedup 1.0000x reference)
#include <cuda_runtime.h>
#include <cuda_fp16.h>
#include <stdint.h>
#include <math.h>

#define N_B 8
#define L_S 1024
#define DM  1024
#define H   16
#define D   64
#define QB  64
#define CH  128
#define THREADS 512
// fold 1/sqrt(64) into exp: exp(0.125*S - m) = ex2(S*EXP_C - m2)
#define EXP_C 0.18033688011112042f
#define LOG2E 1.4426950408889634f

// SMEM byte offsets (hi-only tiles; double-buffered e-stage)
#define SO_KH0  0          // pair0 hi (16KB)
#define SO_KH1  16384      // pair1 hi (16KB)
#define SO_QH   32768      // Q hi (8KB)
#define SO_ESM0 40960      // e-stage buf0: 64 rows x 272B (17408B); head-end: P2
#define SO_ESM1 58368      // e-stage buf1 (17408B)
#define SO_PR3  75776      // 16KB scratch for 3rd D-partial
#define SO_ZS   92160      // 64 x 4 f32 Z partials (1KB)
#define SO_ZI   93184      // 64 f32 invZ (256B)
#define SMEM_SZ 93440

// pre-split fp16 hi tile images (exact smem byte layout), 16KB per (n,h,c)
__device__ char     g_hi[(size_t)16 << 20];                  // 16MB
__device__ uint32_t g_p16[(size_t)16 * 128 * 64 * 512];      // 256MB fp16x2 e-planes
__device__ float    g_invZ[16 * 128 * 64];                   // 512KB

// ---------------- helpers ----------------
__device__ __forceinline__ uint32_t s2u(const void* p) {
    uint32_t a;
    asm("{ .reg .u64 t; cvta.to.shared.u64 t, %1; cvt.u32.u64 %0, t; }" : "=r"(a) : "l"(p));
    return a;
}
__device__ __forceinline__ uint32_t pack_f16(float lo, float hi) {    // lo -> bits[15:0]
    uint32_t r;
    asm("cvt.rn.f16x2.f32 %0, %1, %2;" : "=r"(r) : "f"(hi), "f"(lo));
    return r;
}
__device__ __forceinline__ float2 unpack_f16(uint32_t w) {
    __half2 h = *reinterpret_cast<__half2*>(&w);
    return __half22float2(h);
}
__device__ __forceinline__ float exps(float x, float m2) {   // exp(0.125*x) * 2^-m2
    float r, t = fmaf(x, EXP_C, -m2);
    asm("ex2.approx.ftz.f32 %0, %1;" : "=f"(r) : "f"(t));
    return r;
}

#define LDM4(r, ad) \
    asm volatile("ldmatrix.sync.aligned.m8n8.x4.shared.b16 {%0,%1,%2,%3}, [%4];" \
        : "=r"((r)[0]), "=r"((r)[1]), "=r"((r)[2]), "=r"((r)[3]) : "r"(ad))

#define LDM4T(r, ad) \
    asm volatile("ldmatrix.sync.aligned.m8n8.x4.trans.shared.b16 {%0,%1,%2,%3}, [%4];" \
        : "=r"((r)[0]), "=r"((r)[1]), "=r"((r)[2]), "=r"((r)[3]) : "r"(ad))

#define MMA(c, a, b0_, b1_) \
    asm volatile("mma.sync.aligned.m16n8k16.row.col.f32.f16.f16.f32 " \
        "{%0,%1,%2,%3}, {%4,%5,%6,%7}, {%8,%9}, {%0,%1,%2,%3};" \
        : "+f"((c)[0]), "+f"((c)[1]), "+f"((c)[2]), "+f"((c)[3]) \
        : "r"((a)[0]), "r"((a)[1]), "r"((a)[2]), "r"((a)[3]), "r"(b0_), "r"(b1_))

#define CPA16(sa, g) \
    asm volatile("cp.async.cg.shared.global [%0], [%1], 16;" :: "r"(sa), "l"(g))
#define CPA_COMMIT() asm volatile("cp.async.commit_group;" ::: "memory")
#define CPA_WAIT0()  asm volatile("cp.async.wait_group 0;" ::: "memory")
#define CPA_WAIT1()  asm volatile("cp.async.wait_group 1;" ::: "memory")

// ---------------- preprocess: f32 -> fp16 hi tile images ----------------
extern "C" __global__ void __launch_bounds__(512)
prep_kernel(const float* __restrict__ in)
{
    int idx = blockIdx.x * 512 + threadIdx.x;     // 2M threads, 1 float4 each
    int dqi = idx & 255;                          // h*16 + dq
    int s   = (idx >> 8) & 1023;
    int n   = idx >> 18;
    int dq = dqi & 15;
    float4 v = *(const float4*)(in + (((size_t)(n * 1024 + s)) << 10) + dqi * 4);
    uint32_t h0 = pack_f16(v.x, v.y);
    uint32_t h1 = pack_f16(v.z, v.w);
    uint32_t t = (uint32_t)((n * 16 + (dqi >> 4)) * 8 + (s >> 7));
    uint32_t b = (uint32_t)((s & 127) * 128 + ((dq * 8) ^ ((s & 7) << 4)));
    *(uint2*)(g_hi + (((size_t)t) << 14) + b) = make_uint2(h0, h1);
}

// ---------------- merge: attn = (1/16) sum_h e'_h * invZ'_h ----------------
extern "C" __global__ void __launch_bounds__(256)
merge_kernel(float* __restrict__ attn)
{
    int idx = blockIdx.x * 256 + threadIdx.x;     // 1M threads, 8 s each
    int s8 = idx & 127;                           // uint4 index (8 halfs)
    int qg = (idx >> 7) & 1023;
    int n  = idx >> 17;
    int cta = n * 16 + (qg >> 6);
    int ql  = qg & 63;
    float a0 = 0.f, a1 = 0.f, a2 = 0.f, a3 = 0.f;
    float a4 = 0.f, a5 = 0.f, a6 = 0.f, a7 = 0.f;
    #pragma unroll
    for (int h = 0; h < 16; ++h) {
        int base = (h * 128 + cta) * 64 + ql;
        uint4 w = __ldcs((const uint4*)(g_p16 + (((size_t)base) << 9) + s8 * 4));
        float iz = g_invZ[base];
        float2 v0 = unpack_f16(w.x), v1 = unpack_f16(w.y);
        float2 v2 = unpack_f16(w.z), v3 = unpack_f16(w.w);
        a0 += v0.x * iz; a1 += v0.y * iz; a2 += v1.x * iz; a3 += v1.y * iz;
        a4 += v2.x * iz; a5 += v2.y * iz; a6 += v3.x * iz; a7 += v3.y * iz;
    }
    float* dst = attn + (((size_t)(n * 1024 + qg)) << 10) + s8 * 8;
    const float c16 = 1.f / 16.f;
    *(float4*)(dst)     = make_float4(a0 * c16, a1 * c16, a2 * c16, a3 * c16);
    *(float4*)(dst + 4) = make_float4(a4 * c16, a5 * c16, a6 * c16, a7 * c16);
}

// ---------------- main attention kernel ----------------
extern "C" __global__ void __launch_bounds__(THREADS)
attn_mma_kernel(float* __restrict__ out)
{
    extern __shared__ __align__(1024) char smem[];
    const uint32_t sb = s2u(smem);
    float* ZS = (float*)(smem + SO_ZS);
    float* ZI = (float*)(smem + SO_ZI);
    float* P1 = (float*)(smem + SO_KH1);          // head-end D-partials
    float* P2 = (float*)(smem + SO_ESM0);         // (pending copy is always ESM1)
    float* P3 = (float*)(smem + SO_PR3);

    const int tid  = threadIdx.x;
    const int lane = tid & 31;
    const int warp = tid >> 5;        // 16 warps
    const int qw   = warp & 3;        // q-tile group (16 rows)
    const int sw   = warp >> 2;       // s-quarter (32 cols)
    const int qb   = blockIdx.x, n = blockIdx.y;
    const int q0   = qb * QB;
    const int cta  = n * 16 + qb;

    const int qr   = qw * 16 + (lane >> 2);   // C/A-frag row (q)
    const int tig2 = 2 * (lane & 3);          // col pair base

    // trans-ldmatrix lane geometry for PV B-operand
    const int tg = lane >> 3, tr = lane & 7;
    const uint32_t pv_srow0 = (uint32_t)(sw * 32 + (tg & 1) * 8 + tr);
    const uint32_t pv_dbase = (uint32_t)((tg >> 1) * 8);

    // e-stage copy geometry: thread owns 32B of the logical 16KB chunk image
    const int cq  = tid >> 3;             // q row 0..63
    const int coff = (tid & 7) * 32;      // byte offset in 256B row

    // prologue: prefetch chunk (h=0,c=0) hi tile into pair0
    {
        const size_t tb = ((size_t)(n * 16 * 8)) << 14;     // tile (n,0,0)
        #pragma unroll
        for (int k = 0; k < 2; ++k) {
            uint32_t o = (uint32_t)(k * 512 + tid) * 16;
            CPA16(sb + SO_KH0 + o, g_hi + tb + o);
        }
        CPA_COMMIT();
    }

    uint32_t QHf[4][4];
    float Dacc[8][4];
    float z0 = 0.f, z1 = 0.f;
    float m2a = 0.f, m2b = 0.f;       // per-row exp shift (log2 units)
    size_t pbase = 0, pb_prev = 0;
    int c_prev = 0;

    for (int i = 0; i < H * 8; ++i) {
        const int h = i >> 3, c = i & 7;
        const uint32_t kb = (i & 1) ? SO_KH1 : SO_KH0;
        const uint32_t eb_cur = (i & 1) ? SO_ESM1 : SO_ESM0;

        CPA_WAIT0();
        __syncthreads();   // [A] cur tile resident; prev ESM writes visible

        // ---- coalesced e-plane copy of chunk i-1 (overlaps this chunk) ----
        if (i > 0) {
            const uint32_t eb_prev = ((i - 1) & 1) ? SO_ESM1 : SO_ESM0;
            const char* src = smem + eb_prev + cq * 272 + coff;
            uint4 v0 = *(const uint4*)(src);
            uint4 v1 = *(const uint4*)(src + 16);
            uint32_t* dst = g_p16 + pb_prev + cq * 512 + c_prev * 64 + (coff >> 2);
            __stcs((uint4*)(dst), v0);
            __stcs((uint4*)(dst + 4), v1);
        }

        if (c == 0) {
            // ---- Q hi tile image (8KB), own cp.async group ----
            const size_t tq = ((size_t)((n * 16 + h) * 8 + (qb >> 1))) << 14;
            const size_t qoff = (size_t)(qb & 1) * 8192;
            CPA16(sb + SO_QH + (uint32_t)tid * 16, g_hi + tq + qoff + tid * 16);
            CPA_COMMIT();
        }

        // ---- prefetch chunk i+1 into the other buffer ----
        if (i + 1 < H * 8) {
            const uint32_t dkb = ((i + 1) & 1) ? SO_KH1 : SO_KH0;
            const size_t tt = ((size_t)((n * 16 + ((i + 1) >> 3)) * 8 + ((i + 1) & 7))) << 14;
            #pragma unroll
            for (int k = 0; k < 2; ++k) {
                uint32_t o = (uint32_t)(k * 512 + tid) * 16;
                CPA16(sb + dkb + o, g_hi + tt + o);
            }
            CPA_COMMIT();
        }

        if (c == 0) {
            CPA_WAIT1();       // Q group (older) done; chunk prefetch may fly
            __syncthreads();
            // ---- persistent Q hi fragments ----
            const uint32_t row = qw * 16 + (lane & 15);
            const uint32_t swz = (row & 7) << 4;
            #pragma unroll
            for (int kk = 0; kk < 4; ++kk) {
                uint32_t col = kk * 32 + ((lane >> 4) << 4);
                LDM4(QHf[kk], sb + SO_QH + row * 128 + (col ^ swz));
            }
            // ---- per-row shift: m2 ~= 0.125*|q_row|^2 * log2(e) (hi parts) ----
            {
                float sa = 0.f, sbq = 0.f;
                const int r0 = qr, r1 = qr + 8;
                #pragma unroll
                for (int t = 0; t < 4; ++t) {
                    int dq = (lane & 3) * 4 + t;     // 8B group index 0..15
                    uint32_t b0 = r0 * 128 + ((dq * 8) ^ ((r0 & 7) << 4));
                    uint32_t b1 = r1 * 128 + ((dq * 8) ^ ((r1 & 7) << 4));
                    uint2 w0 = *(uint2*)(smem + SO_QH + b0);
                    uint2 w1 = *(uint2*)(smem + SO_QH + b1);
                    float2 a0 = unpack_f16(w0.x), a1 = unpack_f16(w0.y);
                    float2 c0 = unpack_f16(w1.x), c1 = unpack_f16(w1.y);
                    sa  += a0.x*a0.x + a0.y*a0.y + a1.x*a1.x + a1.y*a1.y;
                    sbq += c0.x*c0.x + c0.y*c0.y + c1.x*c1.x + c1.y*c1.y;
                }
                sa  += __shfl_xor_sync(0xffffffffu, sa, 1);
                sa  += __shfl_xor_sync(0xffffffffu, sa, 2);
                sbq += __shfl_xor_sync(0xffffffffu, sbq, 1);
                sbq += __shfl_xor_sync(0xffffffffu, sbq, 2);
                m2a = sa  * (0.125f * LOG2E);
                m2b = sbq * (0.125f * LOG2E);
            }
            #pragma unroll
            for (int x = 0; x < 8; ++x)
                #pragma unroll
                for (int j = 0; j < 4; ++j) Dacc[x][j] = 0.f;
            z0 = 0.f; z1 = 0.f;
            pbase = ((size_t)(h * 128 + cta)) << 15;
        }

        // ---- QK^T: single-pass fp16 (Qhi*Khi) ----
        float acc[4][4];
        #pragma unroll
        for (int x = 0; x < 4; ++x)
            #pragma unroll
            for (int j = 0; j < 4; ++j) acc[x][j] = 0.f;

        #pragma unroll
        for (int np = 0; np < 2; ++np) {
            const uint32_t rowb = sw * 32 + np * 16 + (lane & 7) + ((lane >> 4) << 3);
            const uint32_t rsw = (rowb & 7) << 4;
            #pragma unroll
            for (int kk = 0; kk < 4; ++kk) {
                uint32_t col = kk * 32 + ((lane >> 3) & 1) * 16;
                uint32_t bh[4];
                LDM4(bh, sb + kb + rowb * 128 + (col ^ rsw));
                MMA(acc[2 * np],     QHf[kk], bh[0], bh[1]);
                MMA(acc[2 * np + 1], QHf[kk], bh[2], bh[3]);
            }
        }

        // ---- shifted exp, Z accumulate, P pack, e' -> ESM[i&1] ----
        uint32_t PH[4][2];
        #pragma unroll
        for (int nt = 0; nt < 4; ++nt) {
            float e0 = exps(acc[nt][0], m2a);
            float e1 = exps(acc[nt][1], m2a);
            float e2 = exps(acc[nt][2], m2b);
            float e3 = exps(acc[nt][3], m2b);
            z0 += e0 + e1; z1 += e2 + e3;
            uint32_t h0 = pack_f16(e0, e1);
            uint32_t h1 = pack_f16(e2, e3);
            PH[nt][0] = h0; PH[nt][1] = h1;
            uint32_t ebo = sw * 64 + nt * 16 + (lane & 3) * 4;
            *(uint32_t*)(smem + eb_cur + qr * 272 + ebo)       = h0;
            *(uint32_t*)(smem + eb_cur + (qr + 8) * 272 + ebo) = h1;
        }

        // ---- PV: single-pass fp16 (Phi*Vhi), V == K tiles ----
        #pragma unroll
        for (int dt = 0; dt < 4; ++dt) {
            const uint32_t dcol = 2 * (pv_dbase + dt * 16);
            #pragma unroll
            for (int kk = 0; kk < 2; ++kk) {
                const uint32_t srow = pv_srow0 + kk * 16;
                uint32_t vh[4];
                LDM4T(vh, sb + kb + srow * 128 + (dcol ^ ((uint32_t)tr << 4)));
                uint32_t aH[4] = {PH[2*kk][0], PH[2*kk][1], PH[2*kk+1][0], PH[2*kk+1][1]};
                MMA(Dacc[2 * dt],     aH, vh[0], vh[1]);
                MMA(Dacc[2 * dt + 1], aH, vh[2], vh[3]);
            }
        }

        if (c == 7) {
            // ---- head end: Z reduce (4 s-quarters per row) ----
            z0 += __shfl_xor_sync(0xffffffffu, z0, 1);
            z0 += __shfl_xor_sync(0xffffffffu, z0, 2);
            z1 += __shfl_xor_sync(0xffffffffu, z1, 1);
            z1 += __shfl_xor_sync(0xffffffffu, z1, 2);
            if ((lane & 3) == 0) {
                ZS[(qw * 16 + (lane >> 2)) * 4 + sw]     = z0;
                ZS[(qw * 16 + (lane >> 2) + 8) * 4 + sw] = z1;
            }
            __syncthreads();   // [F] Z in; tile reads done (KH1 free)
            if (tid < 64) {
                float v = 1.0f / (ZS[4 * tid] + ZS[4 * tid + 1]
                                + ZS[4 * tid + 2] + ZS[4 * tid + 3]);
                ZI[tid] = v;
                g_invZ[(h * 128 + cta) * 64 + tid] = v;
            }

            // sw=1,2,3 publish D partials (KH1 + ESM0 free; ESM1 holds pending)
            if (sw != 0) {
                float* P = (sw == 1) ? P1 : (sw == 2) ? P2 : P3;
                #pragma unroll
                for (int nt = 0; nt < 8; ++nt) {
                    int col = nt * 8 + tig2;
                    *(float2*)(P + qw * 1024 + (lane >> 2) * 64 + col) =
                        make_float2(Dacc[nt][0], Dacc[nt][1]);
                    *(float2*)(P + qw * 1024 + ((lane >> 2) + 8) * 64 + col) =
                        make_float2(Dacc[nt][2], Dacc[nt][3]);
                }
            }
            __syncthreads();   // [G]

            if (sw == 0) {     // reduce 4 partials + normalize + store O
                const float iza = ZI[qw * 16 + (lane >> 2)];
                const float izb = ZI[qw * 16 + (lane >> 2) + 8];
                float* orow0 = out + ((size_t)(n * L_S + q0 + qw * 16 + (lane >> 2))) * DM + h * D;
                float* orow1 = orow0 + (size_t)8 * DM;
                #pragma unroll
                for (int nt = 0; nt < 8; ++nt) {
                    int col = nt * 8 + tig2;
                    int o0 = qw * 1024 + (lane >> 2) * 64 + col;
                    int o1 = qw * 1024 + ((lane >> 2) + 8) * 64 + col;
                    float2 a1 = *(float2*)(P1 + o0), b1 = *(float2*)(P1 + o1);
                    float2 a2 = *(float2*)(P2 + o0), b2 = *(float2*)(P2 + o1);
                    float2 a3 = *(float2*)(P3 + o0), b3 = *(float2*)(P3 + o1);
                    *(float2*)(orow0 + col) = make_float2(
                        (Dacc[nt][0] + a1.x + a2.x + a3.x) * iza,
                        (Dacc[nt][1] + a1.y + a2.y + a3.y) * iza);
                    *(float2*)(orow1 + col) = make_float2(
                        (Dacc[nt][2] + b1.x + b2.x + b3.x) * izb,
                        (Dacc[nt][3] + b1.y + b2.y + b3.y) * izb);
                }
            }
        }

        pb_prev = pbase;
        c_prev = c;
    }

    // ---- epilogue: copy the final chunk's e-plane (ESM1, h=15, c=7) ----
    __syncthreads();
    {
        const char* src = smem + SO_ESM1 + cq * 272 + coff;
        uint4 v0 = *(const uint4*)(src);
        uint4 v1 = *(const uint4*)(src + 16);
        uint32_t* dst = g_p16 + pb_prev + cq * 512 + c_prev * 64 + (coff >> 2);
        __stcs((uint4*)(dst), v0);
        __stcs((uint4*)(dst + 4), v1);
    }
}

extern "C" void kernel_launch(void* const* d_in, const int* in_sizes, int n_in,
                              void* d_out, int out_size) {
    const float* in = (const float*)d_in[0];
    float* out = (float*)d_out;
    const size_t out_elems  = (size_t)N_B * L_S * DM;   // 8,388,608
    const size_t attn_elems = (size_t)N_B * L_S * L_S;  // 8,388,608
    int write_attn = (out_size >= (int)(out_elems + attn_elems)) ? 1 : 0;
    float* attn = out + out_elems;

    cudaFuncSetAttribute(attn_mma_kernel,
                         cudaFuncAttributeMaxDynamicSharedMemorySize, SMEM_SZ);

    prep_kernel<<<4096, 512>>>(in);                     // split to tile images
    dim3 grid(16, 8);                                   // 128 CTAs, 512 threads
    attn_mma_kernel<<<grid, THREADS, SMEM_SZ>>>(out);
    if (write_attn)
        merge_kernel<<<4096, 256>>>(attn);              // attn head-mean
}

// round 15
// speedup vs baseline: 1.0717x; 1.0717x over previous
#include <cuda_runtime.h>
#include <cuda_fp16.h>
#include <stdint.h>
#include <math.h>

#define N_B 8
#define L_S 1024
#define DM  1024
#define H   16
#define D   64
#define QB  64
#define CH  128
#define THREADS 512
// fold 1/sqrt(64) into exp: exp(0.125*S - m) = ex2(S*EXP_C - m2)
#define EXP_C 0.18033688011112042f
#define LOG2E 1.4426950408889634f

// SMEM byte offsets (hi-only tiles)
#define SO_KH0 0          // pair0 hi (16KB)
#define SO_KH1 16384      // pair1 hi (16KB)
#define SO_QH  32768      // Q hi (8KB)
#define SO_P2  40960      // 16KB scratch: 2nd D-partial
#define SO_PR3 58368      // 16KB scratch: 3rd D-partial
#define SO_ZS  74752      // 64 x 4 f32 Z partials (1KB)
#define SO_ZI  75776      // 64 f32 invZ (256B)
#define SMEM_SZ 76032

// pre-split fp16 hi tile images (exact smem byte layout), 16KB per (n,h,c)
__device__ char     g_hi[(size_t)16 << 20];                  // 16MB
__device__ uint32_t g_p16[(size_t)16 * 128 * 64 * 512];      // 256MB fp16x2 e-planes
__device__ float    g_invZ[16 * 128 * 64];                   // 512KB

// ---------------- helpers ----------------
__device__ __forceinline__ uint32_t s2u(const void* p) {
    uint32_t a;
    asm("{ .reg .u64 t; cvta.to.shared.u64 t, %1; cvt.u32.u64 %0, t; }" : "=r"(a) : "l"(p));
    return a;
}
__device__ __forceinline__ uint32_t pack_f16(float lo, float hi) {    // lo -> bits[15:0]
    uint32_t r;
    asm("cvt.rn.f16x2.f32 %0, %1, %2;" : "=r"(r) : "f"(hi), "f"(lo));
    return r;
}
__device__ __forceinline__ float2 unpack_f16(uint32_t w) {
    __half2 h = *reinterpret_cast<__half2*>(&w);
    return __half22float2(h);
}
__device__ __forceinline__ float exps(float x, float m2) {   // exp(0.125*x) * 2^-m2
    float r, t = fmaf(x, EXP_C, -m2);
    asm("ex2.approx.ftz.f32 %0, %1;" : "=f"(r) : "f"(t));
    return r;
}

#define LDM4(r, ad) \
    asm volatile("ldmatrix.sync.aligned.m8n8.x4.shared.b16 {%0,%1,%2,%3}, [%4];" \
        : "=r"((r)[0]), "=r"((r)[1]), "=r"((r)[2]), "=r"((r)[3]) : "r"(ad))

#define LDM4T(r, ad) \
    asm volatile("ldmatrix.sync.aligned.m8n8.x4.trans.shared.b16 {%0,%1,%2,%3}, [%4];" \
        : "=r"((r)[0]), "=r"((r)[1]), "=r"((r)[2]), "=r"((r)[3]) : "r"(ad))

#define MMA(c, a, b0_, b1_) \
    asm volatile("mma.sync.aligned.m16n8k16.row.col.f32.f16.f16.f32 " \
        "{%0,%1,%2,%3}, {%4,%5,%6,%7}, {%8,%9}, {%0,%1,%2,%3};" \
        : "+f"((c)[0]), "+f"((c)[1]), "+f"((c)[2]), "+f"((c)[3]) \
        : "r"((a)[0]), "r"((a)[1]), "r"((a)[2]), "r"((a)[3]), "r"(b0_), "r"(b1_))

#define CPA16(sa, g) \
    asm volatile("cp.async.cg.shared.global [%0], [%1], 16;" :: "r"(sa), "l"(g))
#define CPA_COMMIT() asm volatile("cp.async.commit_group;" ::: "memory")
#define CPA_WAIT0()  asm volatile("cp.async.wait_group 0;" ::: "memory")
#define CPA_WAIT1()  asm volatile("cp.async.wait_group 1;" ::: "memory")

// ---------------- preprocess: f32 -> fp16 hi tile images ----------------
extern "C" __global__ void __launch_bounds__(512)
prep_kernel(const float* __restrict__ in)
{
    int idx = blockIdx.x * 512 + threadIdx.x;     // 2M threads, 1 float4 each
    int dqi = idx & 255;                          // h*16 + dq
    int s   = (idx >> 8) & 1023;
    int n   = idx >> 18;
    int dq = dqi & 15;
    float4 v = *(const float4*)(in + (((size_t)(n * 1024 + s)) << 10) + dqi * 4);
    uint32_t h0 = pack_f16(v.x, v.y);
    uint32_t h1 = pack_f16(v.z, v.w);
    uint32_t t = (uint32_t)((n * 16 + (dqi >> 4)) * 8 + (s >> 7));
    uint32_t b = (uint32_t)((s & 127) * 128 + ((dq * 8) ^ ((s & 7) << 4)));
    *(uint2*)(g_hi + (((size_t)t) << 14) + b) = make_uint2(h0, h1);
}

// ---------------- merge: attn = (1/16) sum_h e'_h * invZ'_h ----------------
extern "C" __global__ void __launch_bounds__(256)
merge_kernel(float* __restrict__ attn)
{
    int idx = blockIdx.x * 256 + threadIdx.x;     // 2.1M threads, 4 s each
    int s4 = idx & 255;                           // uint2 index (4 halfs)
    int qg = (idx >> 8) & 1023;
    int n  = idx >> 18;
    int cta = n * 16 + (qg >> 6);
    int ql  = qg & 63;
    float ax = 0.f, ay = 0.f, az = 0.f, aw = 0.f;
    #pragma unroll
    for (int h = 0; h < 16; ++h) {
        int base = (h * 128 + cta) * 64 + ql;
        uint2 w = *(const uint2*)(g_p16 + (((size_t)base) << 9) + s4 * 2);
        float iz = g_invZ[base];
        float2 v0 = unpack_f16(w.x), v1 = unpack_f16(w.y);
        ax += v0.x * iz; ay += v0.y * iz;
        az += v1.x * iz; aw += v1.y * iz;
    }
    ((float4*)attn)[idx] = make_float4(ax * (1.f / 16.f), ay * (1.f / 16.f),
                                       az * (1.f / 16.f), aw * (1.f / 16.f));
}

// ---------------- main attention kernel ----------------
extern "C" __global__ void __launch_bounds__(THREADS)
attn_mma_kernel(float* __restrict__ out)
{
    extern __shared__ __align__(1024) char smem[];
    const uint32_t sb = s2u(smem);
    float* ZS = (float*)(smem + SO_ZS);
    float* ZI = (float*)(smem + SO_ZI);
    float* P1 = (float*)(smem + SO_KH1);          // head-end D-partials
    float* P2 = (float*)(smem + SO_P2);
    float* P3 = (float*)(smem + SO_PR3);

    const int tid  = threadIdx.x;
    const int lane = tid & 31;
    const int warp = tid >> 5;        // 16 warps
    const int qw   = warp & 3;        // q-tile group (16 rows)
    const int sw   = warp >> 2;       // s-quarter (32 cols)
    const int qb   = blockIdx.x, n = blockIdx.y;
    const int q0   = qb * QB;
    const int cta  = n * 16 + qb;

    const int qr   = qw * 16 + (lane >> 2);   // C/A-frag row (q)
    const int tig2 = 2 * (lane & 3);          // col pair base

    // trans-ldmatrix lane geometry for PV B-operand
    const int tg = lane >> 3, tr = lane & 7;
    const uint32_t pv_srow0 = (uint32_t)(sw * 32 + (tg & 1) * 8 + tr);
    const uint32_t pv_dbase = (uint32_t)((tg >> 1) * 8);

    // direct e-plane store geometry: quad-contiguous 16B segments in [q][s]
    const uint32_t ew = (uint32_t)(sw * 16 + (lane & 3));   // + nt*4 word index

    // prologue: prefetch chunk (h=0,c=0) hi tile into pair0
    {
        const size_t tb = ((size_t)(n * 16 * 8)) << 14;     // tile (n,0,0)
        #pragma unroll
        for (int k = 0; k < 2; ++k) {
            uint32_t o = (uint32_t)(k * 512 + tid) * 16;
            CPA16(sb + SO_KH0 + o, g_hi + tb + o);
        }
        CPA_COMMIT();
    }

    uint32_t QHf[4][4];
    float Dacc[8][4];
    float z0 = 0.f, z1 = 0.f;
    float m2a = 0.f, m2b = 0.f;       // per-row exp shift (log2 units)
    size_t pbase = 0;

    for (int i = 0; i < H * 8; ++i) {
        const int h = i >> 3, c = i & 7;
        const uint32_t kb = (i & 1) ? SO_KH1 : SO_KH0;

        CPA_WAIT0();
        __syncthreads();   // [A] cur tile resident; P-buffers free

        if (c == 0) {
            // ---- Q hi tile image (8KB), own cp.async group ----
            const size_t tq = ((size_t)((n * 16 + h) * 8 + (qb >> 1))) << 14;
            const size_t qoff = (size_t)(qb & 1) * 8192;
            CPA16(sb + SO_QH + (uint32_t)tid * 16, g_hi + tq + qoff + tid * 16);
            CPA_COMMIT();
        }

        // ---- prefetch chunk i+1 into the other buffer ----
        if (i + 1 < H * 8) {
            const uint32_t dkb = ((i + 1) & 1) ? SO_KH1 : SO_KH0;
            const size_t tt = ((size_t)((n * 16 + ((i + 1) >> 3)) * 8 + ((i + 1) & 7))) << 14;
            #pragma unroll
            for (int k = 0; k < 2; ++k) {
                uint32_t o = (uint32_t)(k * 512 + tid) * 16;
                CPA16(sb + dkb + o, g_hi + tt + o);
            }
            CPA_COMMIT();
        }

        if (c == 0) {
            CPA_WAIT1();       // Q group (older) done; chunk prefetch may fly
            __syncthreads();
            // ---- persistent Q hi fragments ----
            const uint32_t row = qw * 16 + (lane & 15);
            const uint32_t swz = (row & 7) << 4;
            #pragma unroll
            for (int kk = 0; kk < 4; ++kk) {
                uint32_t col = kk * 32 + ((lane >> 4) << 4);
                LDM4(QHf[kk], sb + SO_QH + row * 128 + (col ^ swz));
            }
            // ---- per-row shift: m2 ~= 0.125*|q_row|^2 * log2(e) (hi parts) ----
            {
                float sa = 0.f, sbq = 0.f;
                const int r0 = qr, r1 = qr + 8;
                #pragma unroll
                for (int t = 0; t < 4; ++t) {
                    int dq = (lane & 3) * 4 + t;     // 8B group index 0..15
                    uint32_t b0 = r0 * 128 + ((dq * 8) ^ ((r0 & 7) << 4));
                    uint32_t b1 = r1 * 128 + ((dq * 8) ^ ((r1 & 7) << 4));
                    uint2 w0 = *(uint2*)(smem + SO_QH + b0);
                    uint2 w1 = *(uint2*)(smem + SO_QH + b1);
                    float2 a0 = unpack_f16(w0.x), a1 = unpack_f16(w0.y);
                    float2 c0 = unpack_f16(w1.x), c1 = unpack_f16(w1.y);
                    sa  += a0.x*a0.x + a0.y*a0.y + a1.x*a1.x + a1.y*a1.y;
                    sbq += c0.x*c0.x + c0.y*c0.y + c1.x*c1.x + c1.y*c1.y;
                }
                sa  += __shfl_xor_sync(0xffffffffu, sa, 1);
                sa  += __shfl_xor_sync(0xffffffffu, sa, 2);
                sbq += __shfl_xor_sync(0xffffffffu, sbq, 1);
                sbq += __shfl_xor_sync(0xffffffffu, sbq, 2);
                m2a = sa  * (0.125f * LOG2E);
                m2b = sbq * (0.125f * LOG2E);
            }
            #pragma unroll
            for (int x = 0; x < 8; ++x)
                #pragma unroll
                for (int j = 0; j < 4; ++j) Dacc[x][j] = 0.f;
            z0 = 0.f; z1 = 0.f;
            pbase = ((size_t)(h * 128 + cta)) << 15;
        }

        // ---- QK^T: single-pass fp16 (Qhi*Khi) ----
        float acc[4][4];
        #pragma unroll
        for (int x = 0; x < 4; ++x)
            #pragma unroll
            for (int j = 0; j < 4; ++j) acc[x][j] = 0.f;

        #pragma unroll
        for (int np = 0; np < 2; ++np) {
            const uint32_t rowb = sw * 32 + np * 16 + (lane & 7) + ((lane >> 4) << 3);
            const uint32_t rsw = (rowb & 7) << 4;
            #pragma unroll
            for (int kk = 0; kk < 4; ++kk) {
                uint32_t col = kk * 32 + ((lane >> 3) & 1) * 16;
                uint32_t bh[4];
                LDM4(bh, sb + kb + rowb * 128 + (col ^ rsw));
                MMA(acc[2 * np],     QHf[kk], bh[0], bh[1]);
                MMA(acc[2 * np + 1], QHf[kk], bh[2], bh[3]);
            }
        }

        // ---- shifted exp, Z accumulate, P pack, e' -> g_p16 direct ----
        uint32_t PH[4][2];
        {
            uint32_t* erow0 = g_p16 + pbase + (size_t)qr * 512 + c * 64 + ew;
            uint32_t* erow1 = erow0 + (size_t)8 * 512;
            #pragma unroll
            for (int nt = 0; nt < 4; ++nt) {
                float e0 = exps(acc[nt][0], m2a);
                float e1 = exps(acc[nt][1], m2a);
                float e2 = exps(acc[nt][2], m2b);
                float e3 = exps(acc[nt][3], m2b);
                z0 += e0 + e1; z1 += e2 + e3;
                uint32_t h0 = pack_f16(e0, e1);
                uint32_t h1 = pack_f16(e2, e3);
                PH[nt][0] = h0; PH[nt][1] = h1;
                erow0[nt * 4] = h0;       // quad-contiguous 16B segments
                erow1[nt * 4] = h1;
            }
        }

        // ---- PV: single-pass fp16 (Phi*Vhi), V == K tiles ----
        #pragma unroll
        for (int dt = 0; dt < 4; ++dt) {
            const uint32_t dcol = 2 * (pv_dbase + dt * 16);
            #pragma unroll
            for (int kk = 0; kk < 2; ++kk) {
                const uint32_t srow = pv_srow0 + kk * 16;
                uint32_t vh[4];
                LDM4T(vh, sb + kb + srow * 128 + (dcol ^ ((uint32_t)tr << 4)));
                uint32_t aH[4] = {PH[2*kk][0], PH[2*kk][1], PH[2*kk+1][0], PH[2*kk+1][1]};
                MMA(Dacc[2 * dt],     aH, vh[0], vh[1]);
                MMA(Dacc[2 * dt + 1], aH, vh[2], vh[3]);
            }
        }

        if (c == 7) {
            // ---- head end: Z reduce (4 s-quarters per row) ----
            z0 += __shfl_xor_sync(0xffffffffu, z0, 1);
            z0 += __shfl_xor_sync(0xffffffffu, z0, 2);
            z1 += __shfl_xor_sync(0xffffffffu, z1, 1);
            z1 += __shfl_xor_sync(0xffffffffu, z1, 2);
            if ((lane & 3) == 0) {
                ZS[(qw * 16 + (lane >> 2)) * 4 + sw]     = z0;
                ZS[(qw * 16 + (lane >> 2) + 8) * 4 + sw] = z1;
            }
            __syncthreads();   // [F] Z in; tile reads done (KH1 free)
            if (tid < 64) {
                float v = 1.0f / (ZS[4 * tid] + ZS[4 * tid + 1]
                                + ZS[4 * tid + 2] + ZS[4 * tid + 3]);
                ZI[tid] = v;
                g_invZ[(h * 128 + cta) * 64 + tid] = v;
            }

            // sw=1,2,3 publish D partials
            if (sw != 0) {
                float* P = (sw == 1) ? P1 : (sw == 2) ? P2 : P3;
                #pragma unroll
                for (int nt = 0; nt < 8; ++nt) {
                    int col = nt * 8 + tig2;
                    *(float2*)(P + qw * 1024 + (lane >> 2) * 64 + col) =
                        make_float2(Dacc[nt][0], Dacc[nt][1]);
                    *(float2*)(P + qw * 1024 + ((lane >> 2) + 8) * 64 + col) =
                        make_float2(Dacc[nt][2], Dacc[nt][3]);
                }
            }
            __syncthreads();   // [G]

            if (sw == 0) {     // reduce 4 partials + normalize + store O
                const float iza = ZI[qw * 16 + (lane >> 2)];
                const float izb = ZI[qw * 16 + (lane >> 2) + 8];
                float* orow0 = out + ((size_t)(n * L_S + q0 + qw * 16 + (lane >> 2))) * DM + h * D;
                float* orow1 = orow0 + (size_t)8 * DM;
                #pragma unroll
                for (int nt = 0; nt < 8; ++nt) {
                    int col = nt * 8 + tig2;
                    int o0 = qw * 1024 + (lane >> 2) * 64 + col;
                    int o1 = qw * 1024 + ((lane >> 2) + 8) * 64 + col;
                    float2 a1 = *(float2*)(P1 + o0), b1 = *(float2*)(P1 + o1);
                    float2 a2 = *(float2*)(P2 + o0), b2 = *(float2*)(P2 + o1);
                    float2 a3 = *(float2*)(P3 + o0), b3 = *(float2*)(P3 + o1);
                    *(float2*)(orow0 + col) = make_float2(
                        (Dacc[nt][0] + a1.x + a2.x + a3.x) * iza,
                        (Dacc[nt][1] + a1.y + a2.y + a3.y) * iza);
                    *(float2*)(orow1 + col) = make_float2(
                        (Dacc[nt][2] + b1.x + b2.x + b3.x) * izb,
                        (Dacc[nt][3] + b1.y + b2.y + b3.y) * izb);
                }
            }
        }
    }
}

extern "C" void kernel_launch(void* const* d_in, const int* in_sizes, int n_in,
                              void* d_out, int out_size) {
    const float* in = (const float*)d_in[0];
    float* out = (float*)d_out;
    const size_t out_elems  = (size_t)N_B * L_S * DM;   // 8,388,608
    const size_t attn_elems = (size_t)N_B * L_S * L_S;  // 8,388,608
    int write_attn = (out_size >= (int)(out_elems + attn_elems)) ? 1 : 0;
    float* attn = out + out_elems;

    cudaFuncSetAttribute(attn_mma_kernel,
                         cudaFuncAttributeMaxDynamicSharedMemorySize, SMEM_SZ);

    prep_kernel<<<4096, 512>>>(in);                     // split to tile images
    dim3 grid(16, 8);                                   // 128 CTAs, 512 threads
    attn_mma_kernel<<<grid, THREADS, SMEM_SZ>>>(out);
    if (write_attn)
        merge_kernel<<<8192, 256>>>(attn);              // attn head-mean
}

// round 16
// speedup vs baseline: 1.0902x; 1.0173x over previous
#include <cuda_runtime.h>
#include <cuda_fp16.h>
#include <stdint.h>
#include <math.h>

#define N_B 8
#define L_S 1024
#define DM  1024
#define H   16
#define D   64
#define QB  64
#define CH  128
#define THREADS 512
// fold 1/sqrt(64) into exp: exp(0.125*S - m) = ex2(S*EXP_C - m2)
#define EXP_C 0.18033688011112042f
#define LOG2E 1.4426950408889634f

// SMEM byte offsets: 4 x 16KB K-buffer ring + Q + scratch
#define SO_KB  0          // ring of 4 tiles, chunk i -> buffer (i&3)*16KB
#define SO_QH  65536      // Q hi (8KB)
#define SO_PR3 73728      // 16KB scratch: 3rd D-partial
#define SO_ZS  90112      // 64 x 4 f32 Z partials (1KB)
#define SO_ZI  91136      // 64 f32 invZ (256B)
#define SMEM_SZ 91392

// pre-split fp16 hi tile images (exact smem byte layout), 16KB per (n,h,c);
// chunk index i = h*8+c is CONTIGUOUS: tile address = ((n*128 + i) << 14)
__device__ char     g_hi[(size_t)16 << 20];                  // 16MB
__device__ uint32_t g_p16[(size_t)16 * 128 * 64 * 512];      // 256MB fp16x2 e-planes
__device__ float    g_invZ[16 * 128 * 64];                   // 512KB

// ---------------- helpers ----------------
__device__ __forceinline__ uint32_t s2u(const void* p) {
    uint32_t a;
    asm("{ .reg .u64 t; cvta.to.shared.u64 t, %1; cvt.u32.u64 %0, t; }" : "=r"(a) : "l"(p));
    return a;
}
__device__ __forceinline__ uint32_t pack_f16(float lo, float hi) {    // lo -> bits[15:0]
    uint32_t r;
    asm("cvt.rn.f16x2.f32 %0, %1, %2;" : "=r"(r) : "f"(hi), "f"(lo));
    return r;
}
__device__ __forceinline__ float2 unpack_f16(uint32_t w) {
    __half2 h = *reinterpret_cast<__half2*>(&w);
    return __half22float2(h);
}
__device__ __forceinline__ float exps(float x, float m2) {   // exp(0.125*x) * 2^-m2
    float r, t = fmaf(x, EXP_C, -m2);
    asm("ex2.approx.ftz.f32 %0, %1;" : "=f"(r) : "f"(t));
    return r;
}

#define LDM4(r, ad) \
    asm volatile("ldmatrix.sync.aligned.m8n8.x4.shared.b16 {%0,%1,%2,%3}, [%4];" \
        : "=r"((r)[0]), "=r"((r)[1]), "=r"((r)[2]), "=r"((r)[3]) : "r"(ad))

#define LDM4T(r, ad) \
    asm volatile("ldmatrix.sync.aligned.m8n8.x4.trans.shared.b16 {%0,%1,%2,%3}, [%4];" \
        : "=r"((r)[0]), "=r"((r)[1]), "=r"((r)[2]), "=r"((r)[3]) : "r"(ad))

#define MMA(c, a, b0_, b1_) \
    asm volatile("mma.sync.aligned.m16n8k16.row.col.f32.f16.f16.f32 " \
        "{%0,%1,%2,%3}, {%4,%5,%6,%7}, {%8,%9}, {%0,%1,%2,%3};" \
        : "+f"((c)[0]), "+f"((c)[1]), "+f"((c)[2]), "+f"((c)[3]) \
        : "r"((a)[0]), "r"((a)[1]), "r"((a)[2]), "r"((a)[3]), "r"(b0_), "r"(b1_))

#define CPA16(sa, g) \
    asm volatile("cp.async.cg.shared.global [%0], [%1], 16;" :: "r"(sa), "l"(g))
#define CPA_COMMIT() asm volatile("cp.async.commit_group;" ::: "memory")
#define CPA_WAIT0()  asm volatile("cp.async.wait_group 0;" ::: "memory")
#define CPA_WAIT1()  asm volatile("cp.async.wait_group 1;" ::: "memory")

// ---------------- preprocess: f32 -> fp16 hi tile images ----------------
extern "C" __global__ void __launch_bounds__(512)
prep_kernel(const float* __restrict__ in)
{
    int idx = blockIdx.x * 512 + threadIdx.x;     // 2M threads, 1 float4 each
    int dqi = idx & 255;                          // h*16 + dq
    int s   = (idx >> 8) & 1023;
    int n   = idx >> 18;
    int dq = dqi & 15;
    float4 v = *(const float4*)(in + (((size_t)(n * 1024 + s)) << 10) + dqi * 4);
    uint32_t h0 = pack_f16(v.x, v.y);
    uint32_t h1 = pack_f16(v.z, v.w);
    uint32_t t = (uint32_t)((n * 16 + (dqi >> 4)) * 8 + (s >> 7));
    uint32_t b = (uint32_t)((s & 127) * 128 + ((dq * 8) ^ ((s & 7) << 4)));
    *(uint2*)(g_hi + (((size_t)t) << 14) + b) = make_uint2(h0, h1);
}

// ---------------- merge: attn = (1/16) sum_h e'_h * invZ'_h ----------------
extern "C" __global__ void __launch_bounds__(256)
merge_kernel(float* __restrict__ attn)
{
    int idx = blockIdx.x * 256 + threadIdx.x;     // 2.1M threads, 4 s each
    int s4 = idx & 255;                           // uint2 index (4 halfs)
    int qg = (idx >> 8) & 1023;
    int n  = idx >> 18;
    int cta = n * 16 + (qg >> 6);
    int ql  = qg & 63;
    float ax = 0.f, ay = 0.f, az = 0.f, aw = 0.f;
    #pragma unroll
    for (int h = 0; h < 16; ++h) {
        int base = (h * 128 + cta) * 64 + ql;
        uint2 w = *(const uint2*)(g_p16 + (((size_t)base) << 9) + s4 * 2);
        float iz = g_invZ[base];
        float2 v0 = unpack_f16(w.x), v1 = unpack_f16(w.y);
        ax += v0.x * iz; ay += v0.y * iz;
        az += v1.x * iz; aw += v1.y * iz;
    }
    ((float4*)attn)[idx] = make_float4(ax * (1.f / 16.f), ay * (1.f / 16.f),
                                       az * (1.f / 16.f), aw * (1.f / 16.f));
}

// ---------------- main attention kernel ----------------
extern "C" __global__ void __launch_bounds__(THREADS)
attn_mma_kernel(float* __restrict__ out)
{
    extern __shared__ __align__(1024) char smem[];
    const uint32_t sb = s2u(smem);
    float* ZS = (float*)(smem + SO_ZS);
    float* ZI = (float*)(smem + SO_ZI);
    float* P3 = (float*)(smem + SO_PR3);

    const int tid  = threadIdx.x;
    const int lane = tid & 31;
    const int warp = tid >> 5;        // 16 warps
    const int qw   = warp & 3;        // q-tile group (16 rows)
    const int sw   = warp >> 2;       // s-quarter (32 cols)
    const int qb   = blockIdx.x, n = blockIdx.y;
    const int q0   = qb * QB;
    const int cta  = n * 16 + qb;

    const int qr   = qw * 16 + (lane >> 2);   // C/A-frag row (q)
    const int tig2 = 2 * (lane & 3);          // col pair base

    // trans-ldmatrix lane geometry for PV B-operand
    const int tg = lane >> 3, tr = lane & 7;
    const uint32_t pv_srow0 = (uint32_t)(sw * 32 + (tg & 1) * 8 + tr);
    const uint32_t pv_dbase = (uint32_t)((tg >> 1) * 8);

    // direct e-plane store geometry: quad-contiguous 16B segments in [q][s]
    const uint32_t ew = (uint32_t)(sw * 16 + (lane & 3));   // + nt*4 word index

    // prologue: prefetch chunk pair (0,1) into buffers {0,1} (contiguous 32KB)
    {
        const char* src = g_hi + (((size_t)(n * 128)) << 14);
        #pragma unroll
        for (int k = 0; k < 4; ++k) {
            uint32_t o = (uint32_t)(k * 512 + tid) * 16;
            CPA16(sb + SO_KB + o, src + o);
        }
        CPA_COMMIT();
    }

    uint32_t QHf[4][4];
    float Dacc[8][4];
    float z0 = 0.f, z1 = 0.f;
    float m2a = 0.f, m2b = 0.f;       // per-row exp shift (log2 units)
    size_t pbase = 0;

    for (int ii = 0; ii < H * 8; ii += 2) {      // pair loop
        const uint32_t cur  = (ii & 2) ? 32768u : 0u;       // this pair's 32KB
        const uint32_t dstb = (ii & 2) ? 0u : 32768u;       // next pair's 32KB

        CPA_WAIT0();
        __syncthreads();   // [A] pair resident; prev pair buffers free

        if ((ii & 7) == 0) {
            // ---- Q hi tile image (8KB), own cp.async group ----
            const int h = ii >> 3;
            const size_t tq = ((size_t)((n * 16 + h) * 8 + (qb >> 1))) << 14;
            const size_t qoff = (size_t)(qb & 1) * 8192;
            CPA16(sb + SO_QH + (uint32_t)tid * 16, g_hi + tq + qoff + tid * 16);
            CPA_COMMIT();
        }

        // ---- prefetch next pair (chunks ii+2, ii+3; contiguous 32KB) ----
        if (ii + 2 < H * 8) {
            const char* src = g_hi + (((size_t)(n * 128 + ii + 2)) << 14);
            #pragma unroll
            for (int k = 0; k < 4; ++k) {
                uint32_t o = (uint32_t)(k * 512 + tid) * 16;
                CPA16(sb + dstb + o, src + o);
            }
            CPA_COMMIT();
        }

        if ((ii & 7) == 0) {
            CPA_WAIT1();       // Q group (older) done; pair prefetch may fly
            __syncthreads();
            const int h = ii >> 3;
            // ---- persistent Q hi fragments ----
            const uint32_t row = qw * 16 + (lane & 15);
            const uint32_t swz = (row & 7) << 4;
            #pragma unroll
            for (int kk = 0; kk < 4; ++kk) {
                uint32_t col = kk * 32 + ((lane >> 4) << 4);
                LDM4(QHf[kk], sb + SO_QH + row * 128 + (col ^ swz));
            }
            // ---- per-row shift: m2 ~= 0.125*|q_row|^2 * log2(e) (hi parts) ----
            {
                float sa = 0.f, sbq = 0.f;
                const int r0 = qr, r1 = qr + 8;
                #pragma unroll
                for (int t = 0; t < 4; ++t) {
                    int dq = (lane & 3) * 4 + t;     // 8B group index 0..15
                    uint32_t b0 = r0 * 128 + ((dq * 8) ^ ((r0 & 7) << 4));
                    uint32_t b1 = r1 * 128 + ((dq * 8) ^ ((r1 & 7) << 4));
                    uint2 w0 = *(uint2*)(smem + SO_QH + b0);
                    uint2 w1 = *(uint2*)(smem + SO_QH + b1);
                    float2 a0 = unpack_f16(w0.x), a1 = unpack_f16(w0.y);
                    float2 c0 = unpack_f16(w1.x), c1 = unpack_f16(w1.y);
                    sa  += a0.x*a0.x + a0.y*a0.y + a1.x*a1.x + a1.y*a1.y;
                    sbq += c0.x*c0.x + c0.y*c0.y + c1.x*c1.x + c1.y*c1.y;
                }
                sa  += __shfl_xor_sync(0xffffffffu, sa, 1);
                sa  += __shfl_xor_sync(0xffffffffu, sa, 2);
                sbq += __shfl_xor_sync(0xffffffffu, sbq, 1);
                sbq += __shfl_xor_sync(0xffffffffu, sbq, 2);
                m2a = sa  * (0.125f * LOG2E);
                m2b = sbq * (0.125f * LOG2E);
            }
            #pragma unroll
            for (int x = 0; x < 8; ++x)
                #pragma unroll
                for (int j = 0; j < 4; ++j) Dacc[x][j] = 0.f;
            z0 = 0.f; z1 = 0.f;
            pbase = ((size_t)(h * 128 + cta)) << 15;
        }

        // ==== two chunks, no barrier between them ====
        #pragma unroll
        for (int half = 0; half < 2; ++half) {
            const int i = ii + half;
            const int c = i & 7;
            const uint32_t kb = cur + (uint32_t)half * 16384;

            // ---- QK^T: single-pass fp16 (Qhi*Khi) ----
            float acc[4][4];
            #pragma unroll
            for (int x = 0; x < 4; ++x)
                #pragma unroll
                for (int j = 0; j < 4; ++j) acc[x][j] = 0.f;

            #pragma unroll
            for (int np = 0; np < 2; ++np) {
                const uint32_t rowb = sw * 32 + np * 16 + (lane & 7) + ((lane >> 4) << 3);
                const uint32_t rsw = (rowb & 7) << 4;
                #pragma unroll
                for (int kk = 0; kk < 4; ++kk) {
                    uint32_t col = kk * 32 + ((lane >> 3) & 1) * 16;
                    uint32_t bh[4];
                    LDM4(bh, sb + kb + rowb * 128 + (col ^ rsw));
                    MMA(acc[2 * np],     QHf[kk], bh[0], bh[1]);
                    MMA(acc[2 * np + 1], QHf[kk], bh[2], bh[3]);
                }
            }

            // ---- shifted exp, Z accumulate, P pack, e' -> g_p16 direct ----
            uint32_t PH[4][2];
            {
                uint32_t* erow0 = g_p16 + pbase + (size_t)qr * 512 + c * 64 + ew;
                uint32_t* erow1 = erow0 + (size_t)8 * 512;
                #pragma unroll
                for (int nt = 0; nt < 4; ++nt) {
                    float e0 = exps(acc[nt][0], m2a);
                    float e1 = exps(acc[nt][1], m2a);
                    float e2 = exps(acc[nt][2], m2b);
                    float e3 = exps(acc[nt][3], m2b);
                    z0 += e0 + e1; z1 += e2 + e3;
                    uint32_t h0 = pack_f16(e0, e1);
                    uint32_t h1 = pack_f16(e2, e3);
                    PH[nt][0] = h0; PH[nt][1] = h1;
                    erow0[nt * 4] = h0;       // quad-contiguous 16B segments
                    erow1[nt * 4] = h1;
                }
            }

            // ---- PV: single-pass fp16 (Phi*Vhi), V == K tiles ----
            #pragma unroll
            for (int dt = 0; dt < 4; ++dt) {
                const uint32_t dcol = 2 * (pv_dbase + dt * 16);
                #pragma unroll
                for (int kk = 0; kk < 2; ++kk) {
                    const uint32_t srow = pv_srow0 + kk * 16;
                    uint32_t vh[4];
                    LDM4T(vh, sb + kb + srow * 128 + (dcol ^ ((uint32_t)tr << 4)));
                    uint32_t aH[4] = {PH[2*kk][0], PH[2*kk][1], PH[2*kk+1][0], PH[2*kk+1][1]};
                    MMA(Dacc[2 * dt],     aH, vh[0], vh[1]);
                    MMA(Dacc[2 * dt + 1], aH, vh[2], vh[3]);
                }
            }

            if (c == 7) {
                // ---- head end: Z reduce (4 s-quarters per row) ----
                const int h = i >> 3;
                z0 += __shfl_xor_sync(0xffffffffu, z0, 1);
                z0 += __shfl_xor_sync(0xffffffffu, z0, 2);
                z1 += __shfl_xor_sync(0xffffffffu, z1, 1);
                z1 += __shfl_xor_sync(0xffffffffu, z1, 2);
                if ((lane & 3) == 0) {
                    ZS[(qw * 16 + (lane >> 2)) * 4 + sw]     = z0;
                    ZS[(qw * 16 + (lane >> 2) + 8) * 4 + sw] = z1;
                }
                __syncthreads();   // [F] Z in; all tile reads of this pair done
                if (tid < 64) {
                    float v = 1.0f / (ZS[4 * tid] + ZS[4 * tid + 1]
                                    + ZS[4 * tid + 2] + ZS[4 * tid + 3]);
                    ZI[tid] = v;
                    g_invZ[(h * 128 + cta) * 64 + tid] = v;
                }

                // D-partials into this pair's buffers (prefetch targets other pair)
                float* P1 = (float*)(smem + cur);
                float* P2 = (float*)(smem + cur + 16384);
                if (sw != 0) {
                    float* P = (sw == 1) ? P1 : (sw == 2) ? P2 : P3;
                    #pragma unroll
                    for (int nt = 0; nt < 8; ++nt) {
                        int col = nt * 8 + tig2;
                        *(float2*)(P + qw * 1024 + (lane >> 2) * 64 + col) =
                            make_float2(Dacc[nt][0], Dacc[nt][1]);
                        *(float2*)(P + qw * 1024 + ((lane >> 2) + 8) * 64 + col) =
                            make_float2(Dacc[nt][2], Dacc[nt][3]);
                    }
                }
                __syncthreads();   // [G]

                if (sw == 0) {     // reduce 4 partials + normalize + store O
                    const float iza = ZI[qw * 16 + (lane >> 2)];
                    const float izb = ZI[qw * 16 + (lane >> 2) + 8];
                    float* orow0 = out + ((size_t)(n * L_S + q0 + qw * 16 + (lane >> 2))) * DM + h * D;
                    float* orow1 = orow0 + (size_t)8 * DM;
                    #pragma unroll
                    for (int nt = 0; nt < 8; ++nt) {
                        int col = nt * 8 + tig2;
                        int o0 = qw * 1024 + (lane >> 2) * 64 + col;
                        int o1 = qw * 1024 + ((lane >> 2) + 8) * 64 + col;
                        float2 a1 = *(float2*)(P1 + o0), b1 = *(float2*)(P1 + o1);
                        float2 a2 = *(float2*)(P2 + o0), b2 = *(float2*)(P2 + o1);
                        float2 a3 = *(float2*)(P3 + o0), b3 = *(float2*)(P3 + o1);
                        *(float2*)(orow0 + col) = make_float2(
                            (Dacc[nt][0] + a1.x + a2.x + a3.x) * iza,
                            (Dacc[nt][1] + a1.y + a2.y + a3.y) * iza);
                        *(float2*)(orow1 + col) = make_float2(
                            (Dacc[nt][2] + b1.x + b2.x + b3.x) * izb,
                            (Dacc[nt][3] + b1.y + b2.y + b3.y) * izb);
                    }
                }
            }
        }
    }
}

extern "C" void kernel_launch(void* const* d_in, const int* in_sizes, int n_in,
                              void* d_out, int out_size) {
    const float* in = (const float*)d_in[0];
    float* out = (float*)d_out;
    const size_t out_elems  = (size_t)N_B * L_S * DM;   // 8,388,608
    const size_t attn_elems = (size_t)N_B * L_S * L_S;  // 8,388,608
    int write_attn = (out_size >= (int)(out_elems + attn_elems)) ? 1 : 0;
    float* attn = out + out_elems;

    cudaFuncSetAttribute(attn_mma_kernel,
                         cudaFuncAttributeMaxDynamicSharedMemorySize, SMEM_SZ);

    prep_kernel<<<4096, 512>>>(in);                     // split to tile images
    dim3 grid(16, 8);                                   // 128 CTAs, 512 threads
    attn_mma_kernel<<<grid, THREADS, SMEM_SZ>>>(out);
    if (write_attn)
        merge_kernel<<<8192, 256>>>(attn);              // attn head-mean
}

// round 17
// speedup vs baseline: 1.1207x; 1.0280x over previous
#include <cuda_runtime.h>
#include <cuda_fp16.h>
#include <stdint.h>
#include <math.h>

#define N_B 8
#define L_S 1024
#define DM  1024
#define H   16
#define D   64
#define QB  64
#define CH  128
#define THREADS 512
// fold 1/sqrt(64) into exp: exp(0.125*S - m) = ex2(S*EXP_C - m2)
#define EXP_C 0.18033688011112042f
#define LOG2E 1.4426950408889634f

// SMEM byte offsets: 4 x 16KB K-buffer ring + Q + scratch
#define SO_KB  0          // ring of 4 tiles, pair (ii&2) -> 32KB half
#define SO_QH  65536      // Q hi (8KB)
#define SO_PR3 73728      // 16KB scratch: 3rd D-partial
#define SO_ZS  90112      // 64 x 4 f32 Z partials (1KB)
#define SO_ZIA 91136      // 16 x 64 f32 invZ table (4KB)
#define SMEM_SZ 95232

// pre-split fp16 hi tile images (exact smem byte layout), 16KB per (n,h,c);
// chunk index i = h*8+c is CONTIGUOUS: tile address = ((n*128 + i) << 14)
__device__ char     g_hi[(size_t)16 << 20];                  // 16MB
__device__ uint32_t g_p16[(size_t)16 * 128 * 64 * 512];      // 256MB fp16x2 e-planes

// ---------------- helpers ----------------
__device__ __forceinline__ uint32_t s2u(const void* p) {
    uint32_t a;
    asm("{ .reg .u64 t; cvta.to.shared.u64 t, %1; cvt.u32.u64 %0, t; }" : "=r"(a) : "l"(p));
    return a;
}
__device__ __forceinline__ uint32_t pack_f16(float lo, float hi) {    // lo -> bits[15:0]
    uint32_t r;
    asm("cvt.rn.f16x2.f32 %0, %1, %2;" : "=r"(r) : "f"(hi), "f"(lo));
    return r;
}
__device__ __forceinline__ float2 unpack_f16(uint32_t w) {
    __half2 h = *reinterpret_cast<__half2*>(&w);
    return __half22float2(h);
}
__device__ __forceinline__ float exps(float x, float m2) {   // exp(0.125*x) * 2^-m2
    float r, t = fmaf(x, EXP_C, -m2);
    asm("ex2.approx.ftz.f32 %0, %1;" : "=f"(r) : "f"(t));
    return r;
}

#define LDM4(r, ad) \
    asm volatile("ldmatrix.sync.aligned.m8n8.x4.shared.b16 {%0,%1,%2,%3}, [%4];" \
        : "=r"((r)[0]), "=r"((r)[1]), "=r"((r)[2]), "=r"((r)[3]) : "r"(ad))

#define LDM4T(r, ad) \
    asm volatile("ldmatrix.sync.aligned.m8n8.x4.trans.shared.b16 {%0,%1,%2,%3}, [%4];" \
        : "=r"((r)[0]), "=r"((r)[1]), "=r"((r)[2]), "=r"((r)[3]) : "r"(ad))

#define MMA(c, a, b0_, b1_) \
    asm volatile("mma.sync.aligned.m16n8k16.row.col.f32.f16.f16.f32 " \
        "{%0,%1,%2,%3}, {%4,%5,%6,%7}, {%8,%9}, {%0,%1,%2,%3};" \
        : "+f"((c)[0]), "+f"((c)[1]), "+f"((c)[2]), "+f"((c)[3]) \
        : "r"((a)[0]), "r"((a)[1]), "r"((a)[2]), "r"((a)[3]), "r"(b0_), "r"(b1_))

#define CPA16(sa, g) \
    asm volatile("cp.async.cg.shared.global [%0], [%1], 16;" :: "r"(sa), "l"(g))
#define CPA_COMMIT() asm volatile("cp.async.commit_group;" ::: "memory")
#define CPA_WAIT0()  asm volatile("cp.async.wait_group 0;" ::: "memory")
#define CPA_WAIT1()  asm volatile("cp.async.wait_group 1;" ::: "memory")

// ---------------- preprocess: f32 -> fp16 hi tile images ----------------
extern "C" __global__ void __launch_bounds__(512)
prep_kernel(const float* __restrict__ in)
{
    int idx = blockIdx.x * 512 + threadIdx.x;     // 2M threads, 1 float4 each
    int dqi = idx & 255;                          // h*16 + dq
    int s   = (idx >> 8) & 1023;
    int n   = idx >> 18;
    int dq = dqi & 15;
    float4 v = *(const float4*)(in + (((size_t)(n * 1024 + s)) << 10) + dqi * 4);
    uint32_t h0 = pack_f16(v.x, v.y);
    uint32_t h1 = pack_f16(v.z, v.w);
    uint32_t t = (uint32_t)((n * 16 + (dqi >> 4)) * 8 + (s >> 7));
    uint32_t b = (uint32_t)((s & 127) * 128 + ((dq * 8) ^ ((s & 7) << 4)));
    *(uint2*)(g_hi + (((size_t)t) << 14) + b) = make_uint2(h0, h1);
}

// ---------------- main attention kernel (with fused attn merge tail) -------
extern "C" __global__ void __launch_bounds__(THREADS)
attn_mma_kernel(float* __restrict__ out, float* __restrict__ attn, int write_attn)
{
    extern __shared__ __align__(1024) char smem[];
    const uint32_t sb = s2u(smem);
    float* ZS  = (float*)(smem + SO_ZS);
    float* ZIA = (float*)(smem + SO_ZIA);    // [h][64] invZ table
    float* P3  = (float*)(smem + SO_PR3);

    const int tid  = threadIdx.x;
    const int lane = tid & 31;
    const int warp = tid >> 5;        // 16 warps
    const int qw   = warp & 3;        // q-tile group (16 rows)
    const int sw   = warp >> 2;       // s-quarter (32 cols)
    const int qb   = blockIdx.x, n = blockIdx.y;
    const int q0   = qb * QB;
    const int cta  = n * 16 + qb;

    const int qr   = qw * 16 + (lane >> 2);   // C/A-frag row (q)
    const int tig2 = 2 * (lane & 3);          // col pair base

    // trans-ldmatrix lane geometry for PV B-operand
    const int tg = lane >> 3, tr = lane & 7;
    const uint32_t pv_srow0 = (uint32_t)(sw * 32 + (tg & 1) * 8 + tr);
    const uint32_t pv_dbase = (uint32_t)((tg >> 1) * 8);

    // direct e-plane store geometry: quad-contiguous 16B segments in [q][s]
    const uint32_t ew = (uint32_t)(sw * 16 + (lane & 3));   // + nt*4 word index

    // prologue: prefetch chunk pair (0,1) into buffers {0,1} (contiguous 32KB)
    {
        const char* src = g_hi + (((size_t)(n * 128)) << 14);
        #pragma unroll
        for (int k = 0; k < 4; ++k) {
            uint32_t o = (uint32_t)(k * 512 + tid) * 16;
            CPA16(sb + SO_KB + o, src + o);
        }
        CPA_COMMIT();
    }

    uint32_t QHf[4][4];
    float Dacc[8][4];
    float z0 = 0.f, z1 = 0.f;
    float m2a = 0.f, m2b = 0.f;       // per-row exp shift (log2 units)
    size_t pbase = 0;

    for (int ii = 0; ii < H * 8; ii += 2) {      // pair loop
        const uint32_t cur  = (ii & 2) ? 32768u : 0u;       // this pair's 32KB
        const uint32_t dstb = (ii & 2) ? 0u : 32768u;       // next pair's 32KB

        CPA_WAIT0();
        __syncthreads();   // [A] pair resident; prev pair buffers free

        if ((ii & 7) == 0) {
            // ---- Q hi tile image (8KB), own cp.async group ----
            const int h = ii >> 3;
            const size_t tq = ((size_t)((n * 16 + h) * 8 + (qb >> 1))) << 14;
            const size_t qoff = (size_t)(qb & 1) * 8192;
            CPA16(sb + SO_QH + (uint32_t)tid * 16, g_hi + tq + qoff + tid * 16);
            CPA_COMMIT();
        }

        // ---- prefetch next pair (chunks ii+2, ii+3; contiguous 32KB) ----
        if (ii + 2 < H * 8) {
            const char* src = g_hi + (((size_t)(n * 128 + ii + 2)) << 14);
            #pragma unroll
            for (int k = 0; k < 4; ++k) {
                uint32_t o = (uint32_t)(k * 512 + tid) * 16;
                CPA16(sb + dstb + o, src + o);
            }
            CPA_COMMIT();
        }

        if ((ii & 7) == 0) {
            CPA_WAIT1();       // Q group (older) done; pair prefetch may fly
            __syncthreads();
            const int h = ii >> 3;
            // ---- persistent Q hi fragments ----
            const uint32_t row = qw * 16 + (lane & 15);
            const uint32_t swz = (row & 7) << 4;
            #pragma unroll
            for (int kk = 0; kk < 4; ++kk) {
                uint32_t col = kk * 32 + ((lane >> 4) << 4);
                LDM4(QHf[kk], sb + SO_QH + row * 128 + (col ^ swz));
            }
            // ---- per-row shift: m2 ~= 0.125*|q_row|^2 * log2(e) (hi parts) ----
            {
                float sa = 0.f, sbq = 0.f;
                const int r0 = qr, r1 = qr + 8;
                #pragma unroll
                for (int t = 0; t < 4; ++t) {
                    int dq = (lane & 3) * 4 + t;     // 8B group index 0..15
                    uint32_t b0 = r0 * 128 + ((dq * 8) ^ ((r0 & 7) << 4));
                    uint32_t b1 = r1 * 128 + ((dq * 8) ^ ((r1 & 7) << 4));
                    uint2 w0 = *(uint2*)(smem + SO_QH + b0);
                    uint2 w1 = *(uint2*)(smem + SO_QH + b1);
                    float2 a0 = unpack_f16(w0.x), a1 = unpack_f16(w0.y);
                    float2 c0 = unpack_f16(w1.x), c1 = unpack_f16(w1.y);
                    sa  += a0.x*a0.x + a0.y*a0.y + a1.x*a1.x + a1.y*a1.y;
                    sbq += c0.x*c0.x + c0.y*c0.y + c1.x*c1.x + c1.y*c1.y;
                }
                sa  += __shfl_xor_sync(0xffffffffu, sa, 1);
                sa  += __shfl_xor_sync(0xffffffffu, sa, 2);
                sbq += __shfl_xor_sync(0xffffffffu, sbq, 1);
                sbq += __shfl_xor_sync(0xffffffffu, sbq, 2);
                m2a = sa  * (0.125f * LOG2E);
                m2b = sbq * (0.125f * LOG2E);
            }
            #pragma unroll
            for (int x = 0; x < 8; ++x)
                #pragma unroll
                for (int j = 0; j < 4; ++j) Dacc[x][j] = 0.f;
            z0 = 0.f; z1 = 0.f;
            pbase = ((size_t)(h * 128 + cta)) << 15;
        }

        // ==== two chunks, no barrier between them ====
        #pragma unroll
        for (int half = 0; half < 2; ++half) {
            const int i = ii + half;
            const int c = i & 7;
            const uint32_t kb = cur + (uint32_t)half * 16384;

            // ---- QK^T: single-pass fp16 (Qhi*Khi) ----
            float acc[4][4];
            #pragma unroll
            for (int x = 0; x < 4; ++x)
                #pragma unroll
                for (int j = 0; j < 4; ++j) acc[x][j] = 0.f;

            #pragma unroll
            for (int np = 0; np < 2; ++np) {
                const uint32_t rowb = sw * 32 + np * 16 + (lane & 7) + ((lane >> 4) << 3);
                const uint32_t rsw = (rowb & 7) << 4;
                #pragma unroll
                for (int kk = 0; kk < 4; ++kk) {
                    uint32_t col = kk * 32 + ((lane >> 3) & 1) * 16;
                    uint32_t bh[4];
                    LDM4(bh, sb + kb + rowb * 128 + (col ^ rsw));
                    MMA(acc[2 * np],     QHf[kk], bh[0], bh[1]);
                    MMA(acc[2 * np + 1], QHf[kk], bh[2], bh[3]);
                }
            }

            // ---- shifted exp, Z accumulate, P pack, e' -> g_p16 direct ----
            uint32_t PH[4][2];
            {
                uint32_t* erow0 = g_p16 + pbase + (size_t)qr * 512 + c * 64 + ew;
                uint32_t* erow1 = erow0 + (size_t)8 * 512;
                #pragma unroll
                for (int nt = 0; nt < 4; ++nt) {
                    float e0 = exps(acc[nt][0], m2a);
                    float e1 = exps(acc[nt][1], m2a);
                    float e2 = exps(acc[nt][2], m2b);
                    float e3 = exps(acc[nt][3], m2b);
                    z0 += e0 + e1; z1 += e2 + e3;
                    uint32_t h0 = pack_f16(e0, e1);
                    uint32_t h1 = pack_f16(e2, e3);
                    PH[nt][0] = h0; PH[nt][1] = h1;
                    erow0[nt * 4] = h0;       // quad-contiguous 16B segments
                    erow1[nt * 4] = h1;
                }
            }

            // ---- PV: single-pass fp16 (Phi*Vhi), V == K tiles ----
            #pragma unroll
            for (int dt = 0; dt < 4; ++dt) {
                const uint32_t dcol = 2 * (pv_dbase + dt * 16);
                #pragma unroll
                for (int kk = 0; kk < 2; ++kk) {
                    const uint32_t srow = pv_srow0 + kk * 16;
                    uint32_t vh[4];
                    LDM4T(vh, sb + kb + srow * 128 + (dcol ^ ((uint32_t)tr << 4)));
                    uint32_t aH[4] = {PH[2*kk][0], PH[2*kk][1], PH[2*kk+1][0], PH[2*kk+1][1]};
                    MMA(Dacc[2 * dt],     aH, vh[0], vh[1]);
                    MMA(Dacc[2 * dt + 1], aH, vh[2], vh[3]);
                }
            }

            if (c == 7) {
                // ---- head end: Z reduce (4 s-quarters per row) ----
                const int h = i >> 3;
                z0 += __shfl_xor_sync(0xffffffffu, z0, 1);
                z0 += __shfl_xor_sync(0xffffffffu, z0, 2);
                z1 += __shfl_xor_sync(0xffffffffu, z1, 1);
                z1 += __shfl_xor_sync(0xffffffffu, z1, 2);
                if ((lane & 3) == 0) {
                    ZS[(qw * 16 + (lane >> 2)) * 4 + sw]     = z0;
                    ZS[(qw * 16 + (lane >> 2) + 8) * 4 + sw] = z1;
                }
                __syncthreads();   // [F] Z in; all tile reads of this pair done
                if (tid < 64) {
                    float v = 1.0f / (ZS[4 * tid] + ZS[4 * tid + 1]
                                    + ZS[4 * tid + 2] + ZS[4 * tid + 3]);
                    ZIA[h * 64 + tid] = v;
                }

                // D-partials into this pair's buffers (prefetch targets other pair)
                float* P1 = (float*)(smem + cur);
                float* P2 = (float*)(smem + cur + 16384);
                if (sw != 0) {
                    float* P = (sw == 1) ? P1 : (sw == 2) ? P2 : P3;
                    #pragma unroll
                    for (int nt = 0; nt < 8; ++nt) {
                        int col = nt * 8 + tig2;
                        *(float2*)(P + qw * 1024 + (lane >> 2) * 64 + col) =
                            make_float2(Dacc[nt][0], Dacc[nt][1]);
                        *(float2*)(P + qw * 1024 + ((lane >> 2) + 8) * 64 + col) =
                            make_float2(Dacc[nt][2], Dacc[nt][3]);
                    }
                }
                __syncthreads();   // [G]

                if (sw == 0) {     // reduce 4 partials + normalize + store O
                    const float iza = ZIA[h * 64 + qw * 16 + (lane >> 2)];
                    const float izb = ZIA[h * 64 + qw * 16 + (lane >> 2) + 8];
                    float* orow0 = out + ((size_t)(n * L_S + q0 + qw * 16 + (lane >> 2))) * DM + h * D;
                    float* orow1 = orow0 + (size_t)8 * DM;
                    #pragma unroll
                    for (int nt = 0; nt < 8; ++nt) {
                        int col = nt * 8 + tig2;
                        int o0 = qw * 1024 + (lane >> 2) * 64 + col;
                        int o1 = qw * 1024 + ((lane >> 2) + 8) * 64 + col;
                        float2 a1 = *(float2*)(P1 + o0), b1 = *(float2*)(P1 + o1);
                        float2 a2 = *(float2*)(P2 + o0), b2 = *(float2*)(P2 + o1);
                        float2 a3 = *(float2*)(P3 + o0), b3 = *(float2*)(P3 + o1);
                        *(float2*)(orow0 + col) = make_float2(
                            (Dacc[nt][0] + a1.x + a2.x + a3.x) * iza,
                            (Dacc[nt][1] + a1.y + a2.y + a3.y) * iza);
                        *(float2*)(orow1 + col) = make_float2(
                            (Dacc[nt][2] + b1.x + b2.x + b3.x) * izb,
                            (Dacc[nt][3] + b1.y + b2.y + b3.y) * izb);
                    }
                }
            }
        }
    }

    // ======== fused attn merge tail: attn = (1/16) sum_h e'_h * invZ'_h ====
    if (write_attn) {
        __syncthreads();   // all e-plane writes + ZIA entries visible CTA-wide
        const uint32_t p16base = (uint32_t)cta * (64u * 512u);
        #pragma unroll 2
        for (int p = 0; p < 16; ++p) {
            int pos = p * THREADS + tid;          // 8192 = 64q x 128 s8-positions
            int q = pos >> 7, s8 = pos & 127;
            float a0 = 0.f, a1 = 0.f, a2 = 0.f, a3 = 0.f;
            float a4 = 0.f, a5 = 0.f, a6 = 0.f, a7 = 0.f;
            #pragma unroll
            for (int h = 0; h < 16; ++h) {
                const uint4 w = *(const uint4*)(g_p16
                    + (((size_t)(h * 128) * 64) << 9)
                    + (((size_t)(p16base + q * 512)) ) + s8 * 4);
                const float iz = ZIA[h * 64 + q];
                float2 v0 = unpack_f16(w.x), v1 = unpack_f16(w.y);
                float2 v2 = unpack_f16(w.z), v3 = unpack_f16(w.w);
                a0 += v0.x * iz; a1 += v0.y * iz; a2 += v1.x * iz; a3 += v1.y * iz;
                a4 += v2.x * iz; a5 += v2.y * iz; a6 += v3.x * iz; a7 += v3.y * iz;
            }
            float* dst = attn + (((size_t)(n * 1024 + q0 + q)) << 10) + s8 * 8;
            const float c16 = 1.f / 16.f;
            *(float4*)(dst)     = make_float4(a0 * c16, a1 * c16, a2 * c16, a3 * c16);
            *(float4*)(dst + 4) = make_float4(a4 * c16, a5 * c16, a6 * c16, a7 * c16);
        }
    }
}

extern "C" void kernel_launch(void* const* d_in, const int* in_sizes, int n_in,
                              void* d_out, int out_size) {
    const float* in = (const float*)d_in[0];
    float* out = (float*)d_out;
    const size_t out_elems  = (size_t)N_B * L_S * DM;   // 8,388,608
    const size_t attn_elems = (size_t)N_B * L_S * L_S;  // 8,388,608
    int write_attn = (out_size >= (int)(out_elems + attn_elems)) ? 1 : 0;
    float* attn = out + out_elems;

    cudaFuncSetAttribute(attn_mma_kernel,
                         cudaFuncAttributeMaxDynamicSharedMemorySize, SMEM_SZ);

    prep_kernel<<<4096, 512>>>(in);                     // split to tile images
    dim3 grid(16, 8);                                   // 128 CTAs, 512 threads
    attn_mma_kernel<<<grid, THREADS, SMEM_SZ>>>(out, attn, write_attn);
}